// round 12
// baseline (speedup 1.0000x reference)
#include <cuda_runtime.h>
#include <cuda_bf16.h>
#include <math.h>
#include <stdio.h>

// Problem constants — VALIDATED: in_sizes = {1048576, 200000, 200000} elements
// (cube, uu, vv positional); out_size = 800000; output extent < 6.4 MB
// (R11 probe), assumed 800000 x float32 = real part of the complex result.
#define NCHAN 4
#define NPIX 512
#define GSIZE 1024
#define NVIS 200000
#define JTAP 6
#define ALPHA_F 14.04f   // 2.34 * 6
#define CUBE_N (NCHAN * NPIX * NPIX)       // 1048576
#define OUT_N  (NCHAN * NVIS)              // 800000 float32 outputs (real part)
#define GM     (GSIZE * GSIZE)             // 1048576
#define GMASK  (GM - 1)
#define PI_F 3.14159265358979f

__device__ float2 g_G[GM];      // one channel's grid, 8 MB
__device__ float  g_scale[NPIX];

__device__ __forceinline__ float i0f(float x) {
    if (x < 3.75f) {
        float t = x * (1.0f / 3.75f);
        t *= t;
        return 1.0f + t * (3.5156229f + t * (3.0899424f + t * (1.2067492f +
                    t * (0.2659732f + t * (0.0360768f + t * 0.0045813f)))));
    } else {
        float t = 3.75f / x;
        float p = 0.39894228f + t * (0.01328592f + t * (0.00225319f +
                    t * (-0.00157565f + t * (0.00916281f + t * (-0.02057706f +
                    t * (0.02635537f + t * (-0.01647633f + t * 0.00392377f)))))));
        return p * __expf(x) * rsqrtf(x);
    }
}

// Extent probe: touch exactly one float index.
__global__ void touch_idx_kernel(float* __restrict__ o, int idx) {
    if (o != 0 && threadIdx.x == 0 && blockIdx.x == 0) o[idx] = 0.0f;
}

__global__ void init_scale_kernel() {
    int i = blockIdx.x * blockDim.x + threadIdx.x;
    if (i >= NPIX) return;
    float f = (float)(i - NPIX / 2) * (1.0f / (float)GSIZE);
    float pj = PI_F * (float)JTAP * f;
    float zz = ALPHA_F * ALPHA_F - pj * pj;
    float z = sqrtf(fmaxf(zz, 1e-12f));
    float i0a = i0f(ALPHA_F);
    float kbft = (float)JTAP * sinhf(z) / (z * i0a);
    g_scale[i & (NPIX - 1)] = 1.0f / kbft;
}

// ---------------------------------------------------------------------------
// Row FFT for channel c: one block per active grid row (0..255, 768..1023).
// ---------------------------------------------------------------------------
__global__ __launch_bounds__(256) void rowfft_kernel(const float* __restrict__ cube,
                                                     int c) {
    int b = blockIdx.x;
    int gi = (b < 256) ? b : b + 512;
    int crow = gi & 511;
    float rs = g_scale[(gi < 512) ? ((gi + 256) & 511) : ((gi - 768) & 511)];

    __shared__ float2 buf[GSIZE];
    unsigned rowbase = (unsigned)((c & 3) * NPIX + crow) * NPIX;
    int t = threadIdx.x;

    for (int p = t; p < GSIZE; p += 256) {
        float v = 0.0f;
        int ccol = -1, sidx = 0;
        if (p < 256)        { ccol = p;       sidx = p + 256; }
        else if (p >= 768)  { ccol = p - 512; sidx = p - 768; }
        if (ccol >= 0) {
            unsigned gidx = rowbase + (unsigned)ccol;
            if (gidx < (unsigned)CUBE_N)
                v = cube[gidx] * g_scale[sidx & 511];
        }
        int rp = (int)(__brev((unsigned)p) >> 22);
        buf[rp & 1023] = make_float2(v * rs, 0.0f);
    }
    __syncthreads();

    for (int sh = 0; sh < 10; sh++) {
        int half = 1 << sh;
        float inv_half = 1.0f / (float)half;
        for (int q = t; q < 512; q += 256) {
            int off = q & (half - 1);
            int i0p = (((q >> sh) << (sh + 1)) + off) & 1023;
            int i1p = (i0p + half) & 1023;
            float ang = -PI_F * (float)off * inv_half;
            float sw, cw;
            __sincosf(ang, &sw, &cw);
            float2 a = buf[i0p];
            float2 bb = buf[i1p];
            float2 tt = make_float2(cw * bb.x - sw * bb.y, cw * bb.y + sw * bb.x);
            buf[i0p] = make_float2(a.x + tt.x, a.y + tt.y);
            buf[i1p] = make_float2(a.x - tt.x, a.y - tt.y);
        }
        __syncthreads();
    }

    unsigned base = (unsigned)gi << 10;
    for (int p = t; p < GSIZE; p += 256)
        g_G[(base | (unsigned)p) & GMASK] = buf[p & 1023];
}

// ---------------------------------------------------------------------------
// Column FFT, in-place in g_G: one block per 4-column group.
// ---------------------------------------------------------------------------
__global__ __launch_bounds__(256) void colfft_kernel() {
    int b = blockIdx.x;
    int u0 = b << 2;

    __shared__ float2 buf[GSIZE * 4];    // 32 KB
    int t = threadIdx.x;

    for (int idx = t; idx < GSIZE * 4; idx += 256)
        buf[idx & 4095] = make_float2(0.0f, 0.0f);
    __syncthreads();

    for (int idx = t; idx < 512 * 4; idx += 256) {
        int ar = idx >> 2;
        int col = idx & 3;
        int gr = (ar < 256) ? ar : ar + 512;
        float2 v = g_G[(((unsigned)gr << 10) | (unsigned)(u0 + col)) & GMASK];
        int rp = (int)(__brev((unsigned)gr) >> 22);
        buf[(((rp & 1023) << 2) + col) & 4095] = v;
    }
    __syncthreads();

    for (int sh = 0; sh < 10; sh++) {
        int half = 1 << sh;
        float inv_half = 1.0f / (float)half;
        for (int idx = t; idx < 512 * 4; idx += 256) {
            int col = idx & 3;
            int q = idx >> 2;
            int off = q & (half - 1);
            int i0p = (((q >> sh) << (sh + 1)) + off) & 1023;
            int i1p = (i0p + half) & 1023;
            float ang = -PI_F * (float)off * inv_half;
            float sw, cw;
            __sincosf(ang, &sw, &cw);
            float2 a = buf[((i0p << 2) + col) & 4095];
            float2 bb = buf[((i1p << 2) + col) & 4095];
            float2 tt = make_float2(cw * bb.x - sw * bb.y, cw * bb.y + sw * bb.x);
            buf[((i0p << 2) + col) & 4095] = make_float2(a.x + tt.x, a.y + tt.y);
            buf[((i1p << 2) + col) & 4095] = make_float2(a.x - tt.x, a.y - tt.y);
        }
        __syncthreads();
    }

    for (int idx = t; idx < GSIZE * 4; idx += 256) {
        int v = idx >> 2;
        int col = idx & 3;
        g_G[(((unsigned)v << 10) | (unsigned)(u0 + col)) & GMASK] = buf[idx & 4095];
    }
}

// ---------------------------------------------------------------------------
// Degridding for channel c — writes REAL PART ONLY: out[c*NVIS + m].
// Max float index = OUT_N-1 = 799999 (3.2 MB), matching the probed extent.
// ---------------------------------------------------------------------------
__device__ __forceinline__ float kbw(float u, float inv_i0) {
    float r = u * (1.0f / 3.0f);
    float x = 1.0f - r * r;
    if (x <= 0.0f) return 0.0f;
    return i0f(ALPHA_F * sqrtf(x)) * inv_i0;
}

__global__ __launch_bounds__(256) void degrid_kernel(const float* __restrict__ uu,
                                                     const float* __restrict__ vv,
                                                     float* __restrict__ outf,
                                                     int c) {
    int m = blockIdx.x * blockDim.x + threadIdx.x;
    if (m >= NVIS) return;

    const float inv_i0 = 1.0f / i0f(ALPHA_F);
    const float OMF = (float)(1000.0 * 2.0 * M_PI * (0.005 * M_PI / (180.0 * 3600.0)));
    const float TF  = (float)((double)GSIZE / (2.0 * M_PI));

    float tu = (uu[m] * OMF) * TF;
    float tv = (vv[m] * OMF) * TF;
    float fu = floorf(tu);
    float fv = floorf(tv);
    int ifu = (int)fu;
    int ifv = (int)fv;

    float wu[JTAP], wv[JTAP];
    int iu[JTAP], iv[JTAP];
#pragma unroll
    for (int j = 0; j < JTAP; j++) {
        float du = tu - (fu + (float)(j - 2));
        float dv = tv - (fv + (float)(j - 2));
        wu[j] = kbw(du, inv_i0);
        wv[j] = kbw(dv, inv_i0);
        iu[j] = (ifu + j - 2 + 4096) & (GSIZE - 1);
        iv[j] = (ifv + j - 2 + 4096) & (GSIZE - 1);
    }

    float accx = 0.0f;
#pragma unroll
    for (int i = 0; i < JTAP; i++) {
        unsigned rvbase = (unsigned)iv[i] << 10;
        float wvi = wv[i];
#pragma unroll
        for (int j = 0; j < JTAP; j++) {
            float w = wvi * wu[j];
            float2 val = g_G[(rvbase | (unsigned)iu[j]) & GMASK];
            accx = fmaf(val.x, w, accx);
        }
    }

    const float CELL2 = 0.005f * 0.005f;
    unsigned o = (unsigned)(c & 3) * NVIS + (unsigned)m;
    if (o < (unsigned)OUT_N) outf[o] = accx * CELL2;
}

// Sync-probe: only on the non-captured (correctness) call.
static int g_capturing = 0;
static void _sp(const char* tag) {
    if (g_capturing) return;
    cudaError_t e = cudaDeviceSynchronize();
    fprintf(stderr, "[s:%s=%d]", tag, (int)e);
    fflush(stderr);
}

extern "C" void kernel_launch(void* const* d_in, const int* in_sizes, int n_in,
                              void* d_out, int out_size) {
    const float* cube = (n_in > 0) ? (const float*)d_in[0] : 0;
    const float* uu   = (n_in > 1) ? (const float*)d_in[1] : 0;
    const float* vv   = (n_in > 2) ? (const float*)d_in[2] : 0;
    float* outf = (float*)d_out;
    if (!cube || !uu || !vv || !outf) return;

    cudaStreamCaptureStatus cs = cudaStreamCaptureStatusNone;
    cudaStreamIsCapturing((cudaStream_t)0, &cs);
    g_capturing = (cs != cudaStreamCaptureStatusNone);

    // Ascending extent probes (max index == what degrid will write anyway).
    touch_idx_kernel<<<1, 32>>>(outf, 0);          _sp("e0");
    touch_idx_kernel<<<1, 32>>>(outf, 399999);     _sp("e1");
    touch_idx_kernel<<<1, 32>>>(outf, OUT_N - 1);  _sp("e2");

    init_scale_kernel<<<2, 256>>>();
    for (int c = 0; c < NCHAN; c++) {
        rowfft_kernel<<<512, 256>>>(cube, c);
        colfft_kernel<<<256, 256>>>();
        degrid_kernel<<<(NVIS + 255) / 256, 256>>>(uu, vv, outf, c);
    }
    _sp("end");
    if (!g_capturing) { fprintf(stderr, "\n"); fflush(stderr); }
}

// round 13
// speedup vs baseline: 1.2675x; 1.2675x over previous
#include <cuda_runtime.h>
#include <cuda_bf16.h>
#include <math.h>

// Problem constants — VALIDATED by R9/R11/R12 telemetry:
// inputs positional {cube:1048576, uu:200000, vv:200000} float32 elements;
// output 800000 float32 = REAL PART of complex visibilities, layout [c][m].
#define NCHAN 4
#define NPIX 512
#define GSIZE 1024
#define NVIS 200000
#define JTAP 6
#define ALPHA_F 14.04f   // 2.34 * 6
#define CUBE_N (NCHAN * NPIX * NPIX)
#define OUT_N  (NCHAN * NVIS)
#define GM     (GSIZE * GSIZE)
#define GMASK  (GM - 1)
#define PI_F 3.14159265358979f

// Scratch: complex intermediate after row FFTs (33.5 MB) + real-only final
// grids, planar per channel (16.8 MB). Statics proven safe in R12.
__device__ float2 g_Gc[NCHAN * GM];
__device__ float  g_Fr[NCHAN * GM];
__device__ float  g_scale[NPIX];

__device__ __forceinline__ float i0f(float x) {
    if (x < 3.75f) {
        float t = x * (1.0f / 3.75f);
        t *= t;
        return 1.0f + t * (3.5156229f + t * (3.0899424f + t * (1.2067492f +
                    t * (0.2659732f + t * (0.0360768f + t * 0.0045813f)))));
    } else {
        float t = 3.75f / x;
        float p = 0.39894228f + t * (0.01328592f + t * (0.00225319f +
                    t * (-0.00157565f + t * (0.00916281f + t * (-0.02057706f +
                    t * (0.02635537f + t * (-0.01647633f + t * 0.00392377f)))))));
        return p * __expf(x) * rsqrtf(x);
    }
}

__global__ void init_scale_kernel() {
    int i = blockIdx.x * blockDim.x + threadIdx.x;
    if (i >= NPIX) return;
    float f = (float)(i - NPIX / 2) * (1.0f / (float)GSIZE);
    float pj = PI_F * (float)JTAP * f;
    float zz = ALPHA_F * ALPHA_F - pj * pj;
    float z = sqrtf(fmaxf(zz, 1e-12f));
    float i0a = i0f(ALPHA_F);
    float kbft = (float)JTAP * sinhf(z) / (z * i0a);
    g_scale[i & (NPIX - 1)] = 1.0f / kbft;
}

// ---------------------------------------------------------------------------
// Row FFT, ALL channels in one launch: 2048 blocks = 4 chan x 512 active rows.
// ---------------------------------------------------------------------------
__global__ __launch_bounds__(256) void rowfft_kernel(const float* __restrict__ cube) {
    int b = blockIdx.x;
    int c = b >> 9;                      // channel
    int ar = b & 511;                    // active row index
    int gi = (ar < 256) ? ar : ar + 512; // grid row (0..255 | 768..1023)
    int crow = gi & 511;
    float rs = g_scale[(gi < 512) ? ((gi + 256) & 511) : ((gi - 768) & 511)];

    __shared__ float2 buf[GSIZE];
    unsigned rowbase = (unsigned)(c * NPIX + crow) * NPIX;
    int t = threadIdx.x;

    for (int p = t; p < GSIZE; p += 256) {
        float v = 0.0f;
        int ccol = -1, sidx = 0;
        if (p < 256)        { ccol = p;       sidx = p + 256; }
        else if (p >= 768)  { ccol = p - 512; sidx = p - 768; }
        if (ccol >= 0) {
            unsigned gidx = rowbase + (unsigned)ccol;
            if (gidx < (unsigned)CUBE_N)
                v = cube[gidx] * g_scale[sidx & 511];
        }
        int rp = (int)(__brev((unsigned)p) >> 22);
        buf[rp & 1023] = make_float2(v * rs, 0.0f);
    }
    __syncthreads();

    for (int sh = 0; sh < 10; sh++) {
        int half = 1 << sh;
        float inv_half = 1.0f / (float)half;
        for (int q = t; q < 512; q += 256) {
            int off = q & (half - 1);
            int i0p = (((q >> sh) << (sh + 1)) + off) & 1023;
            int i1p = (i0p + half) & 1023;
            float ang = -PI_F * (float)off * inv_half;
            float sw, cw;
            __sincosf(ang, &sw, &cw);
            float2 a = buf[i0p];
            float2 bb = buf[i1p];
            float2 tt = make_float2(cw * bb.x - sw * bb.y, cw * bb.y + sw * bb.x);
            buf[i0p] = make_float2(a.x + tt.x, a.y + tt.y);
            buf[i1p] = make_float2(a.x - tt.x, a.y - tt.y);
        }
        __syncthreads();
    }

    float2* dst = g_Gc + ((size_t)c << 20) + ((size_t)gi << 10);
    for (int p = t; p < GSIZE; p += 256) dst[p] = buf[p & 1023];
}

// ---------------------------------------------------------------------------
// Column FFT, ALL channels: 1024 blocks = 4 chan x 256 col-groups (4 cols).
// Reads complex active rows from g_Gc; writes REAL PART ONLY to g_Fr.
// ---------------------------------------------------------------------------
__global__ __launch_bounds__(256) void colfft_kernel() {
    int b = blockIdx.x;
    int c = b >> 8;
    int u0 = (b & 255) << 2;

    __shared__ float2 buf[GSIZE * 4];    // 32 KB
    int t = threadIdx.x;

    for (int idx = t; idx < GSIZE * 4; idx += 256)
        buf[idx & 4095] = make_float2(0.0f, 0.0f);
    __syncthreads();

    const float2* src = g_Gc + ((size_t)c << 20);
    for (int idx = t; idx < 512 * 4; idx += 256) {
        int ar = idx >> 2;
        int col = idx & 3;
        int gr = (ar < 256) ? ar : ar + 512;
        float2 v = src[((unsigned)gr << 10) | (unsigned)(u0 + col)];
        int rp = (int)(__brev((unsigned)gr) >> 22);
        buf[(((rp & 1023) << 2) + col) & 4095] = v;
    }
    __syncthreads();

    for (int sh = 0; sh < 10; sh++) {
        int half = 1 << sh;
        float inv_half = 1.0f / (float)half;
        for (int idx = t; idx < 512 * 4; idx += 256) {
            int col = idx & 3;
            int q = idx >> 2;
            int off = q & (half - 1);
            int i0p = (((q >> sh) << (sh + 1)) + off) & 1023;
            int i1p = (i0p + half) & 1023;
            float ang = -PI_F * (float)off * inv_half;
            float sw, cw;
            __sincosf(ang, &sw, &cw);
            float2 a = buf[((i0p << 2) + col) & 4095];
            float2 bb = buf[((i1p << 2) + col) & 4095];
            float2 tt = make_float2(cw * bb.x - sw * bb.y, cw * bb.y + sw * bb.x);
            buf[((i0p << 2) + col) & 4095] = make_float2(a.x + tt.x, a.y + tt.y);
            buf[((i1p << 2) + col) & 4095] = make_float2(a.x - tt.x, a.y - tt.y);
        }
        __syncthreads();
    }

    float* dst = g_Fr + ((size_t)c << 20);
    for (int idx = t; idx < GSIZE * 4; idx += 256) {
        int v = idx >> 2;
        int col = idx & 3;
        dst[((unsigned)v << 10) | (unsigned)(u0 + col)] = buf[idx & 4095].x;
    }
}

// ---------------------------------------------------------------------------
// Degridding, ALL channels fused: weights computed ONCE per visibility,
// 36 real-valued taps gathered per channel. out[c*NVIS + m] = Re part.
// ---------------------------------------------------------------------------
__device__ __forceinline__ float kbw(float u, float inv_i0) {
    float r = u * (1.0f / 3.0f);
    float x = 1.0f - r * r;
    if (x <= 0.0f) return 0.0f;
    return i0f(ALPHA_F * sqrtf(x)) * inv_i0;
}

__global__ __launch_bounds__(256) void degrid_kernel(const float* __restrict__ uu,
                                                     const float* __restrict__ vv,
                                                     float* __restrict__ outf) {
    int m = blockIdx.x * blockDim.x + threadIdx.x;
    if (m >= NVIS) return;

    const float inv_i0 = 1.0f / i0f(ALPHA_F);
    const float OMF = (float)(1000.0 * 2.0 * M_PI * (0.005 * M_PI / (180.0 * 3600.0)));
    const float TF  = (float)((double)GSIZE / (2.0 * M_PI));

    float tu = (uu[m] * OMF) * TF;
    float tv = (vv[m] * OMF) * TF;
    float fu = floorf(tu);
    float fv = floorf(tv);
    int ifu = (int)fu;
    int ifv = (int)fv;

    float wu[JTAP], wv[JTAP];
    int iu[JTAP], iv[JTAP];
#pragma unroll
    for (int j = 0; j < JTAP; j++) {
        float du = tu - (fu + (float)(j - 2));
        float dv = tv - (fv + (float)(j - 2));
        wu[j] = kbw(du, inv_i0);
        wv[j] = kbw(dv, inv_i0);
        iu[j] = (ifu + j - 2 + 4096) & (GSIZE - 1);
        iv[j] = (ifv + j - 2 + 4096) & (GSIZE - 1);
    }

    float acc[NCHAN];
#pragma unroll
    for (int c = 0; c < NCHAN; c++) acc[c] = 0.0f;

#pragma unroll
    for (int i = 0; i < JTAP; i++) {
        unsigned rvbase = (unsigned)iv[i] << 10;
        float wvi = wv[i];
#pragma unroll
        for (int c = 0; c < NCHAN; c++) {
            const float* plane = g_Fr + ((size_t)c << 20) + rvbase;
            float s = 0.0f;
#pragma unroll
            for (int j = 0; j < JTAP; j++)
                s = fmaf(plane[iu[j]], wu[j], s);
            acc[c] = fmaf(s, wvi, acc[c]);
        }
    }

    const float CELL2 = 0.005f * 0.005f;
#pragma unroll
    for (int c = 0; c < NCHAN; c++) {
        unsigned o = (unsigned)c * NVIS + (unsigned)m;
        if (o < (unsigned)OUT_N) outf[o] = acc[c] * CELL2;
    }
}

extern "C" void kernel_launch(void* const* d_in, const int* in_sizes, int n_in,
                              void* d_out, int out_size) {
    const float* cube = (n_in > 0) ? (const float*)d_in[0] : 0;
    const float* uu   = (n_in > 1) ? (const float*)d_in[1] : 0;
    const float* vv   = (n_in > 2) ? (const float*)d_in[2] : 0;
    float* outf = (float*)d_out;
    if (!cube || !uu || !vv || !outf) return;

    init_scale_kernel<<<2, 256>>>();
    rowfft_kernel<<<NCHAN * 512, 256>>>(cube);
    colfft_kernel<<<NCHAN * 256, 256>>>();
    degrid_kernel<<<(NVIS + 255) / 256, 256>>>(uu, vv, outf);
}

// round 14
// speedup vs baseline: 1.7633x; 1.3912x over previous
#include <cuda_runtime.h>
#include <cuda_bf16.h>
#include <math.h>

// Problem constants — VALIDATED by R9/R11/R12 telemetry:
// inputs positional {cube:1048576, uu:200000, vv:200000} float32 elements;
// output 800000 float32 = REAL PART of complex visibilities, layout [c][m].
#define NCHAN 4
#define NPIX 512
#define GSIZE 1024
#define NVIS 200000
#define JTAP 6
#define ALPHA_F 14.04f   // 2.34 * 6
#define CUBE_N (NCHAN * NPIX * NPIX)
#define OUT_N  (NCHAN * NVIS)
#define GM     (GSIZE * GSIZE)
#define PI_F 3.14159265358979f

// Scratch: complex intermediate after row FFTs (33.5 MB) + channel-interleaved
// real final grid [v][u][c] as float4 (16.8 MB).
__device__ float2 g_Gc[NCHAN * GM];
__device__ float4 g_Fri[GM];
__device__ float  g_scale[NPIX];

__device__ __forceinline__ float i0f(float x) {
    if (x < 3.75f) {
        float t = x * (1.0f / 3.75f);
        t *= t;
        return 1.0f + t * (3.5156229f + t * (3.0899424f + t * (1.2067492f +
                    t * (0.2659732f + t * (0.0360768f + t * 0.0045813f)))));
    } else {
        float t = 3.75f / x;
        float p = 0.39894228f + t * (0.01328592f + t * (0.00225319f +
                    t * (-0.00157565f + t * (0.00916281f + t * (-0.02057706f +
                    t * (0.02635537f + t * (-0.01647633f + t * 0.00392377f)))))));
        return p * __expf(x) * rsqrtf(x);
    }
}

__global__ void init_scale_kernel() {
    int i = blockIdx.x * blockDim.x + threadIdx.x;
    if (i >= NPIX) return;
    float f = (float)(i - NPIX / 2) * (1.0f / (float)GSIZE);
    float pj = PI_F * (float)JTAP * f;
    float zz = ALPHA_F * ALPHA_F - pj * pj;
    float z = sqrtf(fmaxf(zz, 1e-12f));
    float i0a = i0f(ALPHA_F);
    float kbft = (float)JTAP * sinhf(z) / (z * i0a);
    g_scale[i & (NPIX - 1)] = 1.0f / kbft;
}

// ---------------------------------------------------------------------------
// Row FFT, all channels: 2048 blocks = 4 chan x 512 active rows.
// ---------------------------------------------------------------------------
__global__ __launch_bounds__(256) void rowfft_kernel(const float* __restrict__ cube) {
    int b = blockIdx.x;
    int c = b >> 9;
    int ar = b & 511;
    int gi = (ar < 256) ? ar : ar + 512;
    int crow = gi & 511;
    float rs = g_scale[(gi < 512) ? ((gi + 256) & 511) : ((gi - 768) & 511)];

    __shared__ float2 buf[GSIZE];
    unsigned rowbase = (unsigned)(c * NPIX + crow) * NPIX;
    int t = threadIdx.x;

    for (int p = t; p < GSIZE; p += 256) {
        float v = 0.0f;
        int ccol = -1, sidx = 0;
        if (p < 256)        { ccol = p;       sidx = p + 256; }
        else if (p >= 768)  { ccol = p - 512; sidx = p - 768; }
        if (ccol >= 0) {
            unsigned gidx = rowbase + (unsigned)ccol;
            if (gidx < (unsigned)CUBE_N)
                v = cube[gidx] * g_scale[sidx & 511];
        }
        int rp = (int)(__brev((unsigned)p) >> 22);
        buf[rp & 1023] = make_float2(v * rs, 0.0f);
    }
    __syncthreads();

    for (int sh = 0; sh < 10; sh++) {
        int half = 1 << sh;
        float inv_half = 1.0f / (float)half;
        for (int q = t; q < 512; q += 256) {
            int off = q & (half - 1);
            int i0p = (((q >> sh) << (sh + 1)) + off) & 1023;
            int i1p = (i0p + half) & 1023;
            float ang = -PI_F * (float)off * inv_half;
            float sw, cw;
            __sincosf(ang, &sw, &cw);
            float2 a = buf[i0p];
            float2 bb = buf[i1p];
            float2 tt = make_float2(cw * bb.x - sw * bb.y, cw * bb.y + sw * bb.x);
            buf[i0p] = make_float2(a.x + tt.x, a.y + tt.y);
            buf[i1p] = make_float2(a.x - tt.x, a.y - tt.y);
        }
        __syncthreads();
    }

    float2* dst = g_Gc + ((size_t)c << 20) + ((size_t)gi << 10);
    for (int p = t; p < GSIZE; p += 256) dst[p] = buf[p & 1023];
}

// ---------------------------------------------------------------------------
// Column FFT, all channels: 1024 blocks = 4 chan x 256 col-groups (4 cols).
// Reads complex active rows from g_Gc; writes REAL part into the channel-
// interleaved grid g_Fri[v][u].c  (component c of the float4).
// ---------------------------------------------------------------------------
__global__ __launch_bounds__(256) void colfft_kernel() {
    int b = blockIdx.x;
    int c = b >> 8;
    int u0 = (b & 255) << 2;

    __shared__ float2 buf[GSIZE * 4];    // 32 KB
    int t = threadIdx.x;

    for (int idx = t; idx < GSIZE * 4; idx += 256)
        buf[idx & 4095] = make_float2(0.0f, 0.0f);
    __syncthreads();

    const float2* src = g_Gc + ((size_t)c << 20);
    for (int idx = t; idx < 512 * 4; idx += 256) {
        int ar = idx >> 2;
        int col = idx & 3;
        int gr = (ar < 256) ? ar : ar + 512;
        float2 v = src[((unsigned)gr << 10) | (unsigned)(u0 + col)];
        int rp = (int)(__brev((unsigned)gr) >> 22);
        buf[(((rp & 1023) << 2) + col) & 4095] = v;
    }
    __syncthreads();

    for (int sh = 0; sh < 10; sh++) {
        int half = 1 << sh;
        float inv_half = 1.0f / (float)half;
        for (int idx = t; idx < 512 * 4; idx += 256) {
            int col = idx & 3;
            int q = idx >> 2;
            int off = q & (half - 1);
            int i0p = (((q >> sh) << (sh + 1)) + off) & 1023;
            int i1p = (i0p + half) & 1023;
            float ang = -PI_F * (float)off * inv_half;
            float sw, cw;
            __sincosf(ang, &sw, &cw);
            float2 a = buf[((i0p << 2) + col) & 4095];
            float2 bb = buf[((i1p << 2) + col) & 4095];
            float2 tt = make_float2(cw * bb.x - sw * bb.y, cw * bb.y + sw * bb.x);
            buf[((i0p << 2) + col) & 4095] = make_float2(a.x + tt.x, a.y + tt.y);
            buf[((i1p << 2) + col) & 4095] = make_float2(a.x - tt.x, a.y - tt.y);
        }
        __syncthreads();
    }

    // Scatter real part into interleaved layout: float index ((v<<10)|u)*4 + c
    float* dsts = (float*)g_Fri;
    for (int idx = t; idx < GSIZE * 4; idx += 256) {
        int v = idx >> 2;
        int col = idx & 3;
        unsigned cell = ((unsigned)v << 10) | (unsigned)(u0 + col);
        dsts[(cell << 2) + (unsigned)c] = buf[idx & 4095].x;
    }
}

// ---------------------------------------------------------------------------
// Degridding, all channels fused: 36 float4 gathers per visibility (one per
// tap, all 4 channels per load). out[c*NVIS + m] = real part.
// ---------------------------------------------------------------------------
__device__ __forceinline__ float kbw(float u, float inv_i0) {
    float r = u * (1.0f / 3.0f);
    float x = 1.0f - r * r;
    if (x <= 0.0f) return 0.0f;
    return i0f(ALPHA_F * sqrtf(x)) * inv_i0;
}

__global__ __launch_bounds__(256) void degrid_kernel(const float* __restrict__ uu,
                                                     const float* __restrict__ vv,
                                                     float* __restrict__ outf) {
    int m = blockIdx.x * blockDim.x + threadIdx.x;
    if (m >= NVIS) return;

    const float inv_i0 = 1.0f / i0f(ALPHA_F);
    const float OMF = (float)(1000.0 * 2.0 * M_PI * (0.005 * M_PI / (180.0 * 3600.0)));
    const float TF  = (float)((double)GSIZE / (2.0 * M_PI));

    float tu = (uu[m] * OMF) * TF;
    float tv = (vv[m] * OMF) * TF;
    float fu = floorf(tu);
    float fv = floorf(tv);
    int ifu = (int)fu;
    int ifv = (int)fv;

    float wu[JTAP], wv[JTAP];
    int iu[JTAP], iv[JTAP];
#pragma unroll
    for (int j = 0; j < JTAP; j++) {
        float du = tu - (fu + (float)(j - 2));
        float dv = tv - (fv + (float)(j - 2));
        wu[j] = kbw(du, inv_i0);
        wv[j] = kbw(dv, inv_i0);
        iu[j] = (ifu + j - 2 + 4096) & (GSIZE - 1);
        iv[j] = (ifv + j - 2 + 4096) & (GSIZE - 1);
    }

    float a0 = 0.0f, a1 = 0.0f, a2 = 0.0f, a3 = 0.0f;
#pragma unroll
    for (int i = 0; i < JTAP; i++) {
        unsigned rvbase = (unsigned)iv[i] << 10;
        float wvi = wv[i];
        float s0 = 0.0f, s1 = 0.0f, s2 = 0.0f, s3 = 0.0f;
#pragma unroll
        for (int j = 0; j < JTAP; j++) {
            float4 v4 = g_Fri[rvbase | (unsigned)iu[j]];
            float w = wu[j];
            s0 = fmaf(v4.x, w, s0);
            s1 = fmaf(v4.y, w, s1);
            s2 = fmaf(v4.z, w, s2);
            s3 = fmaf(v4.w, w, s3);
        }
        a0 = fmaf(s0, wvi, a0);
        a1 = fmaf(s1, wvi, a1);
        a2 = fmaf(s2, wvi, a2);
        a3 = fmaf(s3, wvi, a3);
    }

    const float CELL2 = 0.005f * 0.005f;
    outf[m]            = a0 * CELL2;
    outf[NVIS + m]     = a1 * CELL2;
    outf[2 * NVIS + m] = a2 * CELL2;
    outf[3 * NVIS + m] = a3 * CELL2;
}

extern "C" void kernel_launch(void* const* d_in, const int* in_sizes, int n_in,
                              void* d_out, int out_size) {
    const float* cube = (n_in > 0) ? (const float*)d_in[0] : 0;
    const float* uu   = (n_in > 1) ? (const float*)d_in[1] : 0;
    const float* vv   = (n_in > 2) ? (const float*)d_in[2] : 0;
    float* outf = (float*)d_out;
    if (!cube || !uu || !vv || !outf) return;

    init_scale_kernel<<<2, 256>>>();
    rowfft_kernel<<<NCHAN * 512, 256>>>(cube);
    colfft_kernel<<<NCHAN * 256, 256>>>();
    degrid_kernel<<<(NVIS + 255) / 256, 256>>>(uu, vv, outf);
}

// round 15
// speedup vs baseline: 2.0607x; 1.1687x over previous
#include <cuda_runtime.h>
#include <cuda_bf16.h>
#include <math.h>

// Problem constants — VALIDATED by R9/R11/R12 telemetry:
// inputs positional {cube:1048576, uu:200000, vv:200000} float32 elements;
// output 800000 float32 = REAL PART of complex visibilities, layout [c][m].
#define NCHAN 4
#define NPIX 512
#define GSIZE 1024
#define NVIS 200000
#define JTAP 6
#define ALPHA_F 14.04f   // 2.34 * 6
#define CUBE_N (NCHAN * NPIX * NPIX)
#define OUT_N  (NCHAN * NVIS)
#define GM     (GSIZE * GSIZE)
#define PI_F 3.14159265358979f

// Scratch: complex intermediate after row FFTs + channel-interleaved real grid.
__device__ float2 g_Gc[NCHAN * GM];
__device__ float4 g_Fri[GM];

__device__ __forceinline__ float i0f(float x) {
    if (x < 3.75f) {
        float t = x * (1.0f / 3.75f);
        t *= t;
        return 1.0f + t * (3.5156229f + t * (3.0899424f + t * (1.2067492f +
                    t * (0.2659732f + t * (0.0360768f + t * 0.0045813f)))));
    } else {
        float t = 3.75f / x;
        float p = 0.39894228f + t * (0.01328592f + t * (0.00225319f +
                    t * (-0.00157565f + t * (0.00916281f + t * (-0.02057706f +
                    t * (0.02635537f + t * (-0.01647633f + t * 0.00392377f)))))));
        return p * __expf(x) * rsqrtf(x);
    }
}

// 1 / kb_ft((i-256)/1024)
__device__ __forceinline__ float scale_val(int i) {
    float f = (float)(i - NPIX / 2) * (1.0f / (float)GSIZE);
    float pj = PI_F * (float)JTAP * f;
    float zz = ALPHA_F * ALPHA_F - pj * pj;
    float z = sqrtf(fmaxf(zz, 1e-12f));
    float kbft = (float)JTAP * sinhf(z) / (z * i0f(ALPHA_F));
    return 1.0f / kbft;
}

// base-4 digit reversal of 10-bit index (5 digits)
__device__ __forceinline__ int digitrev4(int p) {
    int r = 0;
#pragma unroll
    for (int k = 0; k < 5; k++) r = (r << 2) | ((p >> (2 * k)) & 3);
    return r & 1023;
}

__device__ __forceinline__ float2 cmul(float2 a, float c, float s) {
    return make_float2(a.x * c - a.y * s, a.x * s + a.y * c);
}

// ---------------------------------------------------------------------------
// Row FFT, radix-4 (5 stages), all channels: 2048 blocks.
// Scale table computed in-block (no separate init kernel).
// ---------------------------------------------------------------------------
__global__ __launch_bounds__(256) void rowfft_kernel(const float* __restrict__ cube) {
    int b = blockIdx.x;
    int c = b >> 9;
    int ar = b & 511;
    int gi = (ar < 256) ? ar : ar + 512;
    int crow = gi & 511;

    __shared__ float2 buf[GSIZE];
    __shared__ float sc[NPIX];
    int t = threadIdx.x;

    for (int i = t; i < NPIX; i += 256) sc[i] = scale_val(i);
    __syncthreads();

    float rs = sc[(gi < 512) ? gi + 256 : gi - 768];
    const float* src = cube + (size_t)(c * NPIX + crow) * NPIX;

    for (int p = t; p < GSIZE; p += 256) {
        float v = 0.0f;
        if (p < 256)        v = src[p] * sc[p + 256];
        else if (p >= 768)  v = src[p - 512] * sc[p - 768];
        buf[digitrev4(p)] = make_float2(v * rs, 0.0f);
    }
    __syncthreads();

#pragma unroll
    for (int s = 0; s < 5; s++) {
        int q = 1 << (2 * s);
        int bi = t;                                   // 256 butterflies
        int off = bi & (q - 1);
        int i0 = ((bi >> (2 * s)) << (2 * s + 2)) + off;
        float ang = -PI_F * (float)off / (float)(2 * q);
        float s1, c1;
        __sincosf(ang, &s1, &c1);
        float c2 = c1 * c1 - s1 * s1, s2 = 2.0f * c1 * s1;
        float c3 = c2 * c1 - s2 * s1, s3 = s2 * c1 + c2 * s1;

        float2 y0 = buf[i0];
        float2 y1 = cmul(buf[i0 + q], c1, s1);
        float2 y2 = cmul(buf[i0 + 2 * q], c2, s2);
        float2 y3 = cmul(buf[i0 + 3 * q], c3, s3);

        float2 a  = make_float2(y0.x + y2.x, y0.y + y2.y);
        float2 bb = make_float2(y0.x - y2.x, y0.y - y2.y);
        float2 cc = make_float2(y1.x + y3.x, y1.y + y3.y);
        float2 d  = make_float2(y1.x - y3.x, y1.y - y3.y);

        buf[i0]         = make_float2(a.x + cc.x, a.y + cc.y);
        buf[i0 + q]     = make_float2(bb.x + d.y, bb.y - d.x);   // b - i d
        buf[i0 + 2 * q] = make_float2(a.x - cc.x, a.y - cc.y);
        buf[i0 + 3 * q] = make_float2(bb.x - d.y, bb.y + d.x);   // b + i d
        __syncthreads();
    }

    float2* dst = g_Gc + ((size_t)c << 20) + ((size_t)gi << 10);
    for (int p = t; p < GSIZE; p += 256) dst[p] = buf[p];
}

// ---------------------------------------------------------------------------
// Column FFT, radix-4 (5 stages), 4 columns/block, all channels: 1024 blocks.
// Writes REAL part into channel-interleaved grid g_Fri[v][u].c.
// ---------------------------------------------------------------------------
__global__ __launch_bounds__(256) void colfft_kernel() {
    int b = blockIdx.x;
    int c = b >> 8;
    int u0 = (b & 255) << 2;

    __shared__ float2 buf[GSIZE * 4];    // [pos*4 + col], 32 KB
    int t = threadIdx.x;

    for (int idx = t; idx < GSIZE * 4; idx += 256)
        buf[idx] = make_float2(0.0f, 0.0f);
    __syncthreads();

    const float2* src = g_Gc + ((size_t)c << 20);
    for (int idx = t; idx < 512 * 4; idx += 256) {
        int ar = idx >> 2;
        int col = idx & 3;
        int gr = (ar < 256) ? ar : ar + 512;
        float2 v = src[((unsigned)gr << 10) | (unsigned)(u0 + col)];
        buf[(digitrev4(gr) << 2) + col] = v;
    }
    __syncthreads();

#pragma unroll
    for (int s = 0; s < 5; s++) {
        int q = 1 << (2 * s);
#pragma unroll
        for (int idx = t; idx < 1024; idx += 256) {   // 1024 butterfly-tasks
            int col = idx & 3;
            int bi = idx >> 2;
            int off = bi & (q - 1);
            int i0 = ((bi >> (2 * s)) << (2 * s + 2)) + off;
            float ang = -PI_F * (float)off / (float)(2 * q);
            float s1, c1;
            __sincosf(ang, &s1, &c1);
            float c2 = c1 * c1 - s1 * s1, s2 = 2.0f * c1 * s1;
            float c3 = c2 * c1 - s2 * s1, s3 = s2 * c1 + c2 * s1;

            float2 y0 = buf[(i0 << 2) + col];
            float2 y1 = cmul(buf[((i0 + q) << 2) + col], c1, s1);
            float2 y2 = cmul(buf[((i0 + 2 * q) << 2) + col], c2, s2);
            float2 y3 = cmul(buf[((i0 + 3 * q) << 2) + col], c3, s3);

            float2 a  = make_float2(y0.x + y2.x, y0.y + y2.y);
            float2 bb = make_float2(y0.x - y2.x, y0.y - y2.y);
            float2 cc = make_float2(y1.x + y3.x, y1.y + y3.y);
            float2 d  = make_float2(y1.x - y3.x, y1.y - y3.y);

            buf[(i0 << 2) + col]           = make_float2(a.x + cc.x, a.y + cc.y);
            buf[((i0 + q) << 2) + col]     = make_float2(bb.x + d.y, bb.y - d.x);
            buf[((i0 + 2 * q) << 2) + col] = make_float2(a.x - cc.x, a.y - cc.y);
            buf[((i0 + 3 * q) << 2) + col] = make_float2(bb.x - d.y, bb.y + d.x);
        }
        __syncthreads();
    }

    float* dsts = (float*)g_Fri;
    for (int idx = t; idx < GSIZE * 4; idx += 256) {
        int v = idx >> 2;
        int col = idx & 3;
        unsigned cell = ((unsigned)v << 10) | (unsigned)(u0 + col);
        dsts[(cell << 2) + (unsigned)c] = buf[idx].x;
    }
}

// ---------------------------------------------------------------------------
// Degridding (unchanged from R14): 36 float4 gathers per visibility.
// ---------------------------------------------------------------------------
__device__ __forceinline__ float kbw(float u, float inv_i0) {
    float r = u * (1.0f / 3.0f);
    float x = 1.0f - r * r;
    if (x <= 0.0f) return 0.0f;
    return i0f(ALPHA_F * sqrtf(x)) * inv_i0;
}

__global__ __launch_bounds__(256) void degrid_kernel(const float* __restrict__ uu,
                                                     const float* __restrict__ vv,
                                                     float* __restrict__ outf) {
    int m = blockIdx.x * blockDim.x + threadIdx.x;
    if (m >= NVIS) return;

    const float inv_i0 = 1.0f / i0f(ALPHA_F);
    const float OMF = (float)(1000.0 * 2.0 * M_PI * (0.005 * M_PI / (180.0 * 3600.0)));
    const float TF  = (float)((double)GSIZE / (2.0 * M_PI));

    float tu = (uu[m] * OMF) * TF;
    float tv = (vv[m] * OMF) * TF;
    float fu = floorf(tu);
    float fv = floorf(tv);
    int ifu = (int)fu;
    int ifv = (int)fv;

    float wu[JTAP], wv[JTAP];
    int iu[JTAP], iv[JTAP];
#pragma unroll
    for (int j = 0; j < JTAP; j++) {
        float du = tu - (fu + (float)(j - 2));
        float dv = tv - (fv + (float)(j - 2));
        wu[j] = kbw(du, inv_i0);
        wv[j] = kbw(dv, inv_i0);
        iu[j] = (ifu + j - 2 + 4096) & (GSIZE - 1);
        iv[j] = (ifv + j - 2 + 4096) & (GSIZE - 1);
    }

    float a0 = 0.0f, a1 = 0.0f, a2 = 0.0f, a3 = 0.0f;
#pragma unroll
    for (int i = 0; i < JTAP; i++) {
        unsigned rvbase = (unsigned)iv[i] << 10;
        float wvi = wv[i];
        float s0 = 0.0f, s1 = 0.0f, s2 = 0.0f, s3 = 0.0f;
#pragma unroll
        for (int j = 0; j < JTAP; j++) {
            float4 v4 = g_Fri[rvbase | (unsigned)iu[j]];
            float w = wu[j];
            s0 = fmaf(v4.x, w, s0);
            s1 = fmaf(v4.y, w, s1);
            s2 = fmaf(v4.z, w, s2);
            s3 = fmaf(v4.w, w, s3);
        }
        a0 = fmaf(s0, wvi, a0);
        a1 = fmaf(s1, wvi, a1);
        a2 = fmaf(s2, wvi, a2);
        a3 = fmaf(s3, wvi, a3);
    }

    const float CELL2 = 0.005f * 0.005f;
    outf[m]            = a0 * CELL2;
    outf[NVIS + m]     = a1 * CELL2;
    outf[2 * NVIS + m] = a2 * CELL2;
    outf[3 * NVIS + m] = a3 * CELL2;
}

extern "C" void kernel_launch(void* const* d_in, const int* in_sizes, int n_in,
                              void* d_out, int out_size) {
    const float* cube = (n_in > 0) ? (const float*)d_in[0] : 0;
    const float* uu   = (n_in > 1) ? (const float*)d_in[1] : 0;
    const float* vv   = (n_in > 2) ? (const float*)d_in[2] : 0;
    float* outf = (float*)d_out;
    if (!cube || !uu || !vv || !outf) return;

    rowfft_kernel<<<NCHAN * 512, 256>>>(cube);
    colfft_kernel<<<NCHAN * 256, 256>>>();
    degrid_kernel<<<(NVIS + 255) / 256, 256>>>(uu, vv, outf);
}

// round 17
// speedup vs baseline: 2.7033x; 1.3118x over previous
#include <cuda_runtime.h>
#include <cuda_bf16.h>
#include <math.h>

// Problem constants — VALIDATED by R9/R11/R12 telemetry:
// inputs positional {cube:1048576, uu:200000, vv:200000} float32 elements;
// output 800000 float32 = REAL PART of complex visibilities, layout [c][m].
#define NCHAN 4
#define NPIX 512
#define GSIZE 1024
#define NVIS 200000
#define JTAP 6
#define ALPHA_F 14.04f   // 2.34 * 6
#define CUBE_N (NCHAN * NPIX * NPIX)
#define OUT_N  (NCHAN * NVIS)
#define GM     (GSIZE * GSIZE)
#define PI_F 3.14159265358979f

// Channel-PAIR packing: pair p holds channels {2p, 2p+1} as real+imag of one
// complex image. g_Gc: after row FFTs (2 pairs). g_Fc: full 2D spectra of the
// pairs. g_Fri: channel-interleaved Re(F) grid for degrid.
__device__ float2 g_Gc[2 * GM];
__device__ float2 g_Fc[2 * GM];
__device__ float4 g_Fri[GM];

__device__ __forceinline__ float i0f(float x) {
    if (x < 3.75f) {
        float t = x * (1.0f / 3.75f);
        t *= t;
        return 1.0f + t * (3.5156229f + t * (3.0899424f + t * (1.2067492f +
                    t * (0.2659732f + t * (0.0360768f + t * 0.0045813f)))));
    } else {
        float t = 3.75f / x;
        float p = 0.39894228f + t * (0.01328592f + t * (0.00225319f +
                    t * (-0.00157565f + t * (0.00916281f + t * (-0.02057706f +
                    t * (0.02635537f + t * (-0.01647633f + t * 0.00392377f)))))));
        return p * __expf(x) * rsqrtf(x);
    }
}

__device__ __forceinline__ float scale_val(int i) {
    float f = (float)(i - NPIX / 2) * (1.0f / (float)GSIZE);
    float pj = PI_F * (float)JTAP * f;
    float zz = ALPHA_F * ALPHA_F - pj * pj;
    float z = sqrtf(fmaxf(zz, 1e-12f));
    float kbft = (float)JTAP * sinhf(z) / (z * i0f(ALPHA_F));
    return 1.0f / kbft;
}

__device__ __forceinline__ int digitrev4(int p) {
    int r = 0;
#pragma unroll
    for (int k = 0; k < 5; k++) r = (r << 2) | ((p >> (2 * k)) & 3);
    return r & 1023;
}

__device__ __forceinline__ float2 cmul(float2 a, float c, float s) {
    return make_float2(a.x * c - a.y * s, a.x * s + a.y * c);
}

// ---------------------------------------------------------------------------
// Row FFT, radix-4, channel-PAIRED: 1024 blocks = 2 pairs x 512 active rows.
// Complex input = scaled row of channel 2p (re) + channel 2p+1 (im).
// ---------------------------------------------------------------------------
__global__ __launch_bounds__(256) void rowfft_kernel(const float* __restrict__ cube) {
    int b = blockIdx.x;
    int pair = b >> 9;                    // 0..1
    int ar = b & 511;
    int gi = (ar < 256) ? ar : ar + 512;
    int crow = gi & 511;

    __shared__ float2 buf[GSIZE];
    __shared__ float sc[NPIX];
    int t = threadIdx.x;

    for (int i = t; i < NPIX; i += 256) sc[i] = scale_val(i);
    __syncthreads();

    float rs = sc[(gi < 512) ? gi + 256 : gi - 768];
    const float* src0 = cube + (size_t)(2 * pair) * NPIX * NPIX + (size_t)crow * NPIX;
    const float* src1 = src0 + (size_t)NPIX * NPIX;

    for (int p = t; p < GSIZE; p += 256) {
        float v0 = 0.0f, v1 = 0.0f;
        if (p < 256) {
            float s = sc[p + 256] * rs;
            v0 = src0[p] * s;
            v1 = src1[p] * s;
        } else if (p >= 768) {
            float s = sc[p - 768] * rs;
            v0 = src0[p - 512] * s;
            v1 = src1[p - 512] * s;
        }
        buf[digitrev4(p)] = make_float2(v0, v1);
    }
    __syncthreads();

#pragma unroll
    for (int s = 0; s < 5; s++) {
        int q = 1 << (2 * s);
        int bi = t;
        int off = bi & (q - 1);
        int i0 = ((bi >> (2 * s)) << (2 * s + 2)) + off;
        float ang = -PI_F * (float)off / (float)(2 * q);
        float s1, c1;
        __sincosf(ang, &s1, &c1);
        float c2 = c1 * c1 - s1 * s1, s2 = 2.0f * c1 * s1;
        float c3 = c2 * c1 - s2 * s1, s3 = s2 * c1 + c2 * s1;

        float2 y0 = buf[i0];
        float2 y1 = cmul(buf[i0 + q], c1, s1);
        float2 y2 = cmul(buf[i0 + 2 * q], c2, s2);
        float2 y3 = cmul(buf[i0 + 3 * q], c3, s3);

        float2 a  = make_float2(y0.x + y2.x, y0.y + y2.y);
        float2 bb = make_float2(y0.x - y2.x, y0.y - y2.y);
        float2 cc = make_float2(y1.x + y3.x, y1.y + y3.y);
        float2 d  = make_float2(y1.x - y3.x, y1.y - y3.y);

        buf[i0]         = make_float2(a.x + cc.x, a.y + cc.y);
        buf[i0 + q]     = make_float2(bb.x + d.y, bb.y - d.x);
        buf[i0 + 2 * q] = make_float2(a.x - cc.x, a.y - cc.y);
        buf[i0 + 3 * q] = make_float2(bb.x - d.y, bb.y + d.x);
        __syncthreads();
    }

    float2* dst = g_Gc + ((size_t)pair << 20) + ((size_t)gi << 10);
    for (int p = t; p < GSIZE; p += 256) dst[p] = buf[p];
}

// ---------------------------------------------------------------------------
// Column FFT, radix-4, 4 cols/block: 512 blocks = 2 pairs x 256 groups.
// Stores the FULL complex pair-spectrum to g_Fc.
// ---------------------------------------------------------------------------
__global__ __launch_bounds__(256) void colfft_kernel() {
    int b = blockIdx.x;
    int pair = b >> 8;
    int u0 = (b & 255) << 2;

    __shared__ float2 buf[GSIZE * 4];
    int t = threadIdx.x;

    for (int idx = t; idx < GSIZE * 4; idx += 256)
        buf[idx] = make_float2(0.0f, 0.0f);
    __syncthreads();

    const float2* src = g_Gc + ((size_t)pair << 20);
    for (int idx = t; idx < 512 * 4; idx += 256) {
        int ar = idx >> 2;
        int col = idx & 3;
        int gr = (ar < 256) ? ar : ar + 512;
        float2 v = src[((unsigned)gr << 10) | (unsigned)(u0 + col)];
        buf[(digitrev4(gr) << 2) + col] = v;
    }
    __syncthreads();

#pragma unroll
    for (int s = 0; s < 5; s++) {
        int q = 1 << (2 * s);
#pragma unroll
        for (int idx = t; idx < 1024; idx += 256) {
            int col = idx & 3;
            int bi = idx >> 2;
            int off = bi & (q - 1);
            int i0 = ((bi >> (2 * s)) << (2 * s + 2)) + off;
            float ang = -PI_F * (float)off / (float)(2 * q);
            float s1, c1;
            __sincosf(ang, &s1, &c1);
            float c2 = c1 * c1 - s1 * s1, s2 = 2.0f * c1 * s1;
            float c3 = c2 * c1 - s2 * s1, s3 = s2 * c1 + c2 * s1;

            float2 y0 = buf[(i0 << 2) + col];
            float2 y1 = cmul(buf[((i0 + q) << 2) + col], c1, s1);
            float2 y2 = cmul(buf[((i0 + 2 * q) << 2) + col], c2, s2);
            float2 y3 = cmul(buf[((i0 + 3 * q) << 2) + col], c3, s3);

            float2 a  = make_float2(y0.x + y2.x, y0.y + y2.y);
            float2 bb = make_float2(y0.x - y2.x, y0.y - y2.y);
            float2 cc = make_float2(y1.x + y3.x, y1.y + y3.y);
            float2 d  = make_float2(y1.x - y3.x, y1.y - y3.y);

            buf[(i0 << 2) + col]           = make_float2(a.x + cc.x, a.y + cc.y);
            buf[((i0 + q) << 2) + col]     = make_float2(bb.x + d.y, bb.y - d.x);
            buf[((i0 + 2 * q) << 2) + col] = make_float2(a.x - cc.x, a.y - cc.y);
            buf[((i0 + 3 * q) << 2) + col] = make_float2(bb.x - d.y, bb.y + d.x);
        }
        __syncthreads();
    }

    float2* dst = g_Fc + ((size_t)pair << 20);
    for (int idx = t; idx < GSIZE * 4; idx += 256) {
        int v = idx >> 2;
        int col = idx & 3;
        dst[((unsigned)v << 10) | (unsigned)(u0 + col)] = buf[idx];
    }
}

// ---------------------------------------------------------------------------
// Unpack: Re of each channel via Hermitian symmetry of the pair spectra.
//   Re F_{2p}[k]  = (Re Fp[k] + Re Fp[-k]) / 2
//   Re F_{2p+1}[k]= (Im Fp[k] + Im Fp[-k]) / 2
// ---------------------------------------------------------------------------
__global__ __launch_bounds__(256) void unpack_kernel() {
    unsigned idx = blockIdx.x * 256u + threadIdx.x;
    if (idx >= (unsigned)GM) return;
    unsigned v = idx >> 10;
    unsigned u = idx & 1023;
    unsigned mv = (GSIZE - v) & 1023;
    unsigned mu = (GSIZE - u) & 1023;
    unsigned midx = (mv << 10) | mu;

    float2 f0  = g_Fc[idx];
    float2 f0m = g_Fc[midx];
    float2 f1  = g_Fc[GM + idx];
    float2 f1m = g_Fc[GM + midx];

    g_Fri[idx] = make_float4(0.5f * (f0.x + f0m.x),
                             0.5f * (f0.y + f0m.y),
                             0.5f * (f1.x + f1m.x),
                             0.5f * (f1.y + f1m.y));
}

// ---------------------------------------------------------------------------
// Degridding (unchanged): 36 float4 gathers per visibility.
// ---------------------------------------------------------------------------
__device__ __forceinline__ float kbw(float u, float inv_i0) {
    float r = u * (1.0f / 3.0f);
    float x = 1.0f - r * r;
    if (x <= 0.0f) return 0.0f;
    return i0f(ALPHA_F * sqrtf(x)) * inv_i0;
}

__global__ __launch_bounds__(256) void degrid_kernel(const float* __restrict__ uu,
                                                     const float* __restrict__ vv,
                                                     float* __restrict__ outf) {
    int m = blockIdx.x * blockDim.x + threadIdx.x;
    if (m >= NVIS) return;

    const float inv_i0 = 1.0f / i0f(ALPHA_F);
    const float OMF = (float)(1000.0 * 2.0 * M_PI * (0.005 * M_PI / (180.0 * 3600.0)));
    const float TF  = (float)((double)GSIZE / (2.0 * M_PI));

    float tu = (uu[m] * OMF) * TF;
    float tv = (vv[m] * OMF) * TF;
    float fu = floorf(tu);
    float fv = floorf(tv);
    int ifu = (int)fu;
    int ifv = (int)fv;

    float wu[JTAP], wv[JTAP];
    int iu[JTAP], iv[JTAP];
#pragma unroll
    for (int j = 0; j < JTAP; j++) {
        float du = tu - (fu + (float)(j - 2));
        float dv = tv - (fv + (float)(j - 2));
        wu[j] = kbw(du, inv_i0);
        wv[j] = kbw(dv, inv_i0);
        iu[j] = (ifu + j - 2 + 4096) & (GSIZE - 1);
        iv[j] = (ifv + j - 2 + 4096) & (GSIZE - 1);
    }

    float a0 = 0.0f, a1 = 0.0f, a2 = 0.0f, a3 = 0.0f;
#pragma unroll
    for (int i = 0; i < JTAP; i++) {
        unsigned rvbase = (unsigned)iv[i] << 10;
        float wvi = wv[i];
        float s0 = 0.0f, s1 = 0.0f, s2 = 0.0f, s3 = 0.0f;
#pragma unroll
        for (int j = 0; j < JTAP; j++) {
            float4 v4 = g_Fri[rvbase | (unsigned)iu[j]];
            float w = wu[j];
            s0 = fmaf(v4.x, w, s0);
            s1 = fmaf(v4.y, w, s1);
            s2 = fmaf(v4.z, w, s2);
            s3 = fmaf(v4.w, w, s3);
        }
        a0 = fmaf(s0, wvi, a0);
        a1 = fmaf(s1, wvi, a1);
        a2 = fmaf(s2, wvi, a2);
        a3 = fmaf(s3, wvi, a3);
    }

    const float CELL2 = 0.005f * 0.005f;
    outf[m]            = a0 * CELL2;
    outf[NVIS + m]     = a1 * CELL2;
    outf[2 * NVIS + m] = a2 * CELL2;
    outf[3 * NVIS + m] = a3 * CELL2;
}

extern "C" void kernel_launch(void* const* d_in, const int* in_sizes, int n_in,
                              void* d_out, int out_size) {
    const float* cube = (n_in > 0) ? (const float*)d_in[0] : 0;
    const float* uu   = (n_in > 1) ? (const float*)d_in[1] : 0;
    const float* vv   = (n_in > 2) ? (const float*)d_in[2] : 0;
    float* outf = (float*)d_out;
    if (!cube || !uu || !vv || !outf) return;

    rowfft_kernel<<<2 * 512, 256>>>(cube);
    colfft_kernel<<<2 * 256, 256>>>();
    unpack_kernel<<<GM / 256, 256>>>();
    degrid_kernel<<<(NVIS + 255) / 256, 256>>>(uu, vv, outf);
}